// round 6
// baseline (speedup 1.0000x reference)
#include <cuda_runtime.h>

// ---------------------------------------------------------------------------
// Sparse 125-tap equivariant convolution, N=200000 points in 192^3 grid.
// v3b: upfront probe + counting-sort by tap, register-double-buffered
//      weight/feat staging, q folded into pre-expanded w4v.
//      (identical compute to v3; removed static guard per harness rules)
// ---------------------------------------------------------------------------

#define GRIDL 192
#define NVOX  (192*192*192)
#define NTAP  125
#define TILE  256
#define CH    28            // hits per chunk
#define LIST_CAP 2048       // max hits per CTA (mean ~1154, sigma ~30)
#define WSM_SZ 3328         // w1(1024)+w2(512)+w3(256)+w4v(1536)

__device__ float g_emb[NTAP * 8];
__device__ float g_v3[NTAP * 3];
__device__ float g_W[NTAP * 2304];
__device__ int   g_vol[NVOX];

// ---- prep 1: radial embedding + spherical vector per tap -------------------
__global__ void k_prep1() {
    int p = threadIdx.x;
    if (p >= NTAP) return;
    float dx = (float)(p / 25) - 2.f;
    float dy = (float)((p / 5) % 5) - 2.f;
    float dz = (float)(p % 5) - 2.f;
    float d = sqrtf(dx * dx + dy * dy + dz * dz);
    const float step = 2.5f / 9.f;
    for (int r = 0; r < 8; r++) {
        float c = step * (float)(r + 1);
        float t = (d - c) / step;
        float e = 0.f;
        if (fabsf(t) < 1.f) {
            float s = 1.f - t * t;
            e = 1.14136f * expf(2.f) * expf(-2.f / s);
        }
        g_emb[p * 8 + r] = e;
    }
    float inv = (d > 0.f) ? (1.f / fmaxf(d, 1e-9f)) : 0.f;
    const float s3 = 1.7320508075688772f;
    g_v3[p * 3 + 0] = s3 * dx * inv;
    g_v3[p * 3 + 1] = s3 * dy * inv;
    g_v3[p * 3 + 2] = s3 * dz * inv;
}

// ---- prep 2: factored, pre-scaled weights ---------------------------------
__global__ void k_prep2(const float* __restrict__ weight) {
    int p = blockIdx.x;
    __shared__ float e[8];
    if (threadIdx.x < 8) e[threadIdx.x] = g_emb[p * 8 + threadIdx.x];
    __syncthreads();
    const float ALPHA = 0.14433756729740643f;      // 1/sqrt(48)
    const float INV125 = 1.f / 125.f;
    const float INVS3 = 0.5773502691896258f;       // 1/sqrt(3)
    for (int c = threadIdx.x; c < 2304; c += blockDim.x) {
        float s = 0.f;
        #pragma unroll
        for (int r = 0; r < 8; r++) s += e[r] * weight[r * 2304 + c];
        s *= INV125;
        float sc = (c < 1792) ? ALPHA : ALPHA * INVS3;
        g_W[p * 2304 + c] = s * sc;
    }
}

// ---- clear voxel volume to -1 ---------------------------------------------
__global__ void k_zero() {
    int i = blockIdx.x * blockDim.x + threadIdx.x;
    int4 m1 = make_int4(-1, -1, -1, -1);
    if (i < NVOX / 4) ((int4*)g_vol)[i] = m1;
}

// ---- scatter point indices ------------------------------------------------
__global__ void k_scatter(const int* __restrict__ coords, int n) {
    int i = blockIdx.x * blockDim.x + threadIdx.x;
    if (i < n) {
        int x = coords[3 * i], y = coords[3 * i + 1], z = coords[3 * i + 2];
        g_vol[(x * GRIDL + y) * GRIDL + z] = i;
    }
}

// ---- main -----------------------------------------------------------------
__global__ void __launch_bounds__(256, 2)
k_main(const float* __restrict__ feats,
       const float* __restrict__ wsc0,
       const float* __restrict__ wsc1,
       float* __restrict__ out, int n,
       const int* __restrict__ coords)
{
    extern __shared__ float sm[];
    float* acc  = sm;                              // TILE*80
    float* wsm  = acc + TILE * 80;                 // WSM_SZ
    float* fbuf = wsm + WSM_SZ;                    // CH*80
    unsigned* sorted = (unsigned*)(fbuf + CH * 80);// LIST_CAP
    int* tstart = (int*)(sorted + LIST_CAP);       // 132
    int* cnt    = tstart + 132;                    // 128

    const int tid = threadIdx.x;
    const int pt0 = blockIdx.x * TILE;
    const int mypt = pt0 + tid;
    const bool valid = (mypt < n);
    int cx = 0, cy = 0, cz = 0;
    if (valid) {
        cx = coords[3 * mypt];
        cy = coords[3 * mypt + 1];
        cz = coords[3 * mypt + 2];
    }

    // ---- phase 0: init counters, stage self weights into wsm (reused) -----
    if (tid < 128) cnt[tid] = 0;
    for (int i = tid; i < 1024; i += 256) wsm[i] = wsc0[i] * 0.17677669529663687f;
    wsm[1024 + tid] = wsc1[tid & 255] * 0.25f;
    __syncthreads();

    // ---- phase 1: self term + probe pass A --------------------------------
    unsigned msk[4] = {0u, 0u, 0u, 0u};
    if (valid) {
        const float* f = feats + (size_t)mypt * 80;
        float fr[48];
        #pragma unroll
        for (int i = 0; i < 32; i++) fr[i] = f[i];
        #pragma unroll
        for (int c = 0; c < 32; c++) {
            float s = 0.f;
            #pragma unroll
            for (int i = 0; i < 32; i++) s += fr[i] * wsm[i * 32 + c];
            acc[tid * 80 + c] = s;
        }
        #pragma unroll
        for (int i = 0; i < 48; i++) fr[i] = f[32 + i];
        #pragma unroll
        for (int k = 0; k < 16; k++) {
            float s0 = 0.f, s1 = 0.f, s2 = 0.f;
            #pragma unroll
            for (int i = 0; i < 16; i++) {
                float w = wsm[1024 + i * 16 + k];
                s0 += fr[i * 3 + 0] * w;
                s1 += fr[i * 3 + 1] * w;
                s2 += fr[i * 3 + 2] * w;
            }
            acc[tid * 80 + 32 + k * 3 + 0] = s0;
            acc[tid * 80 + 32 + k * 3 + 1] = s1;
            acc[tid * 80 + 32 + k * 3 + 2] = s2;
        }
        // probe all 125 taps, record bitmask + counts
        #pragma unroll
        for (int w = 0; w < 4; w++) {
            unsigned mw = 0u;
            #pragma unroll 4
            for (int j = 0; j < 32; j++) {
                int p = w * 32 + j;
                if (p < 125) {
                    int dx = p / 25 - 2, dy = (p / 5) % 5 - 2, dz = p % 5 - 2;
                    int x = cx + dx, y = cy + dy, z = cz + dz;
                    if ((unsigned)x < (unsigned)GRIDL && (unsigned)y < (unsigned)GRIDL &&
                        (unsigned)z < (unsigned)GRIDL) {
                        if (g_vol[(x * GRIDL + y) * GRIDL + z] >= 0) {
                            mw |= (1u << j);
                            atomicAdd(&cnt[p], 1);
                        }
                    }
                }
            }
            msk[w] = mw;
        }
    }
    __syncthreads();

    // ---- phase 2: exclusive scan of per-tap counts (warp 0) ---------------
    if (tid < 32) {
        int b4 = tid * 4;
        int c0 = cnt[b4], c1 = cnt[b4 + 1], c2 = cnt[b4 + 2], c3 = cnt[b4 + 3];
        int s = c0 + c1 + c2 + c3;
        int t = s;
        #pragma unroll
        for (int d = 1; d < 32; d <<= 1) {
            int v = __shfl_up_sync(0xffffffffu, t, d);
            if (tid >= d) t += v;
        }
        int ex = t - s;
        tstart[b4] = ex; ex += c0;
        tstart[b4 + 1] = ex; ex += c1;
        tstart[b4 + 2] = ex; ex += c2;
        tstart[b4 + 3] = ex;
    }
    __syncthreads();
    if (tid < 125) cnt[tid] = tstart[tid];   // cursors
    __syncthreads();

    // ---- phase 3: pass B — re-probe hits, scatter into sorted list -------
    if (valid) {
        #pragma unroll
        for (int w = 0; w < 4; w++) {
            unsigned mw = msk[w];
            while (mw) {
                int j = __ffs(mw) - 1;
                mw &= mw - 1;
                int p = w * 32 + j;
                int dx = p / 25 - 2, dy = (p / 5) % 5 - 2, dz = p % 5 - 2;
                int x = cx + dx, y = cy + dy, z = cz + dz;
                int nb = g_vol[(x * GRIDL + y) * GRIDL + z];
                int pos = atomicAdd(&cnt[p], 1);
                if (pos < LIST_CAP)
                    sorted[pos] = ((unsigned)tid << 18) | (unsigned)nb;
            }
        }
    }
    __syncthreads();

    // ---- phase 4: pipelined tap loop --------------------------------------
    const int lane = tid & 31, wid = tid >> 5;
    const int kA = lane / 3, nA = lane - 3 * kA;
    const int lb = lane + 32;
    const int kBr = lb / 3, nB = lb - 3 * kBr;
    const int kB = (lane < 16) ? kBr : 0;

    float wpf[9], fpf[9];
    float vpf0 = 0.f, vpf1 = 0.f, vpf2 = 0.f;
    float v0 = 0.f, v1 = 0.f, v2 = 0.f;

    auto load_chunk = [&](int p, int b, bool lw) {
        if (lw) {
            const float* wg = g_W + p * 2304;
            #pragma unroll
            for (int k = 0; k < 9; k++) {
                int e = tid + k * 256;
                if (e < 2304) wpf[k] = wg[e];
            }
            vpf0 = g_v3[3 * p]; vpf1 = g_v3[3 * p + 1]; vpf2 = g_v3[3 * p + 2];
        }
        int s = tstart[p];
        int c = min(CH, tstart[p + 1] - s - b);
        #pragma unroll
        for (int k = 0; k < 9; k++) {
            int e = tid + k * 256;
            if (e < c * 80) {
                int h = e / 80, el = e - 80 * h;
                unsigned rec = sorted[s + b + h];
                fpf[k] = feats[(size_t)(rec & 0x3FFFFu) * 80 + el];
            }
        }
    };

    int curp = 0;
    while (curp < 125 && tstart[curp + 1] == tstart[curp]) curp++;
    int curb = 0;
    bool havew = true;
    if (curp < 125) load_chunk(curp, 0, true);

    while (curp < 125) {
        const int s0 = tstart[curp];
        const int cn = min(CH, tstart[curp + 1] - s0 - curb);

        // STS staged registers into smem
        if (havew) {
            v0 = vpf0; v1 = vpf1; v2 = vpf2;
            #pragma unroll
            for (int k = 0; k < 9; k++) {
                int e = tid + k * 256;
                if (e < 1792) {
                    wsm[e] = wpf[k];
                } else if (e < 2304) {
                    int r = e - 1792;
                    int i = r >> 5, c = r & 31;
                    int bix = 1792 + i * 96 + c;   // j = 3i+m rows of 32
                    float w = wpf[k];
                    wsm[bix]      = v0 * w;
                    wsm[bix + 32] = v1 * w;
                    wsm[bix + 64] = v2 * w;
                }
            }
        }
        #pragma unroll
        for (int k = 0; k < 9; k++) {
            int e = tid + k * 256;
            if (e < cn * 80) fbuf[e] = fpf[k];
        }
        __syncthreads();

        // advance + prefetch next chunk (LDGs overlap with compute below)
        int np = curp, nbb = curb + CH;
        if (s0 + nbb >= tstart[curp + 1]) {
            np = curp + 1; nbb = 0;
            while (np < 125 && tstart[np + 1] == tstart[np]) np++;
        }
        bool wn = (np != curp);
        if (np < 125) load_chunk(np, nbb, wn);

        // compute current chunk: one warp per hit
        {
            const float vA = (nA == 0) ? v0 : ((nA == 1) ? v1 : v2);
            const float vB = (nB == 0) ? v0 : ((nB == 1) ? v1 : v2);
            for (int h = wid; h < cn; h += 8) {
                unsigned rec = sorted[s0 + curb + h];
                const float* fh = fbuf + h * 80;
                float* ap = acc + (rec >> 18) * 80;
                float a0 = 0.f, sA = 0.f, sB = 0.f, aA = 0.f, aB = 0.f;
                #pragma unroll
                for (int i = 0; i < 32; i++) {
                    float fi = fh[i];
                    a0 += fi * wsm[i * 32 + lane];
                    sA += fi * wsm[1024 + i * 16 + kA];
                    sB += fi * wsm[1024 + i * 16 + kB];
                }
                #pragma unroll
                for (int i = 0; i < 16; i++) {
                    aA += fh[32 + 3 * i + nA] * wsm[1536 + i * 16 + kA];
                    aB += fh[32 + 3 * i + nB] * wsm[1536 + i * 16 + kB];
                }
                #pragma unroll
                for (int j = 0; j < 48; j++)
                    a0 += fh[32 + j] * wsm[1792 + j * 32 + lane];
                ap[lane] += a0;
                ap[32 + lane] += vA * sA + aA;
                if (lane < 16) ap[64 + lane] += vB * sB + aB;
            }
        }
        __syncthreads();
        havew = wn; curp = np; curb = nbb;
    }

    // ---- writeout ----------------------------------------------------------
    __syncthreads();
    for (int idx = tid; idx < TILE * 80; idx += 256) {
        int pt = idx / 80, c = idx - pt * 80;
        if (pt0 + pt < n) out[(size_t)(pt0 + pt) * 80 + c] = acc[pt * 80 + c];
    }
}

// ---------------------------------------------------------------------------
extern "C" void kernel_launch(void* const* d_in, const int* in_sizes, int n_in,
                              void* d_out, int out_size) {
    const float* feats  = (const float*)d_in[0];
    const float* weight = (const float*)d_in[1];
    const float* wsc0   = (const float*)d_in[2];
    const float* wsc1   = (const float*)d_in[3];
    const int*   coords = (const int*)d_in[4];
    float* out = (float*)d_out;
    int n = in_sizes[0] / 80;

    const int SMEM = (TILE * 80 + WSM_SZ + CH * 80 + LIST_CAP + 132 + 128) * 4;
    cudaFuncSetAttribute(k_main, cudaFuncAttributeMaxDynamicSharedMemorySize, SMEM);

    k_prep1<<<1, 128>>>();
    k_prep2<<<NTAP, 256>>>(weight);
    k_zero<<<(NVOX / 4 + 255) / 256, 256>>>();
    k_scatter<<<(n + 255) / 256, 256>>>(coords, n);

    int nblk = (n + TILE - 1) / TILE;
    k_main<<<nblk, 256, SMEM>>>(feats, wsc0, wsc1, out, n, coords);
}